// round 14
// baseline (speedup 1.0000x reference)
#include <cuda_runtime.h>
#include <cuda_bf16.h>
#include <math.h>

#define BB 128
#define LL 512
#define DD 128
#define BL (BB*LL)
#define ML 512

// ---------------- scratch (static device globals; no allocations) ----------------
__device__ float g_seqs[BL*DD];
__device__ float g_Q   [BL*DD];
__device__ float g_q   [BL*DD];
__device__ float g_k   [BL*DD];
__device__ float g_v   [BL*DD];
__device__ float g_qp  [BL*DD];
__device__ float g_mha [BL*DD];
__device__ float g_tmp [BL*DD];
__device__ __nv_bfloat16 g_scoresh[BB*LL*LL]; // bf16 raw scores
__device__ __nv_bfloat16 g_attnh  [BB*LL*LL]; // bf16 normalized probs
__device__ __nv_bfloat16 g_Eh     [BL*ML];    // bf16 E
__device__ float g_cape[BL];

// ---------------- helpers ----------------
__device__ __forceinline__ float wredsum(float v){
    #pragma unroll
    for (int o=16;o>0;o>>=1) v += __shfl_xor_sync(0xffffffffu, v, o);
    return v;
}
__device__ __forceinline__ float wredmax(float v){
    #pragma unroll
    for (int o=16;o>0;o>>=1) v = fmaxf(v, __shfl_xor_sync(0xffffffffu, v, o));
    return v;
}
__device__ __forceinline__ void mma_tf32(float* d, const unsigned* a, const unsigned* b){
    asm volatile(
        "mma.sync.aligned.m16n8k8.row.col.f32.tf32.tf32.f32 "
        "{%0,%1,%2,%3},{%4,%5,%6,%7},{%8,%9},{%0,%1,%2,%3};"
        : "+f"(d[0]),"+f"(d[1]),"+f"(d[2]),"+f"(d[3])
        : "r"(a[0]),"r"(a[1]),"r"(a[2]),"r"(a[3]), "r"(b[0]),"r"(b[1]));
}
__device__ __forceinline__ void mma_bf16(float* d, const unsigned* a, const unsigned* b){
    asm volatile(
        "mma.sync.aligned.m16n8k16.row.col.f32.bf16.bf16.f32 "
        "{%0,%1,%2,%3},{%4,%5,%6,%7},{%8,%9},{%0,%1,%2,%3};"
        : "+f"(d[0]),"+f"(d[1]),"+f"(d[2]),"+f"(d[3])
        : "r"(a[0]),"r"(a[1]),"r"(a[2]),"r"(a[3]), "r"(b[0]),"r"(b[1]));
}
__device__ __forceinline__ void cpa16(void* s, const void* g){
    unsigned sa = (unsigned)__cvta_generic_to_shared(s);
    asm volatile("cp.async.cg.shared.global [%0],[%1],16;\n" :: "r"(sa),"l"(g));
}
__device__ __forceinline__ void cp_commit(){ asm volatile("cp.async.commit_group;\n"); }
template<int N> __device__ __forceinline__ void cp_wait(){ asm volatile("cp.async.wait_group %0;\n"::"n"(N)); }
__device__ __forceinline__ unsigned fu(float f){ return __float_as_uint(f); }
__device__ __forceinline__ unsigned pbf2(float a, float b){
    __nv_bfloat162 h = __floats2bfloat162_rn(a,b);
    return *(unsigned*)&h;
}

// ---------------- embedding gather + fused LN1 ----------------
// seqs = item_emb[log_seqs]*sqrt(D); Q = LN1(seqs)
__global__ void embed_ln_k(const float* __restrict__ item, const int* __restrict__ idx,
                           const float* __restrict__ gs, const float* __restrict__ gb,
                           float* __restrict__ seqs, float* __restrict__ Qo){
    int row  = blockIdx.x*8 + (threadIdx.x>>5);
    int lane = threadIdx.x & 31;
    int id = idx[row];
    float4 v = *(const float4*)(item + (long long)id*DD + lane*4);
    const float s = 11.313708498984760f; // sqrt(128)
    v.x*=s; v.y*=s; v.z*=s; v.w*=s;
    *(float4*)(seqs + (long long)row*DD + lane*4) = v;
    float m = wredsum(v.x+v.y+v.z+v.w) * (1.0f/DD);
    float dx=v.x-m, dy=v.y-m, dz=v.z-m, dw=v.w-m;
    float var = wredsum(dx*dx+dy*dy+dz*dz+dw*dw) * (1.0f/DD);
    float r = rsqrtf(var + 1e-8f);
    float4 o;
    o.x = dx*r*gs[lane*4+0] + gb[lane*4+0];
    o.y = dy*r*gs[lane*4+1] + gb[lane*4+1];
    o.z = dz*r*gs[lane*4+2] + gb[lane*4+2];
    o.w = dw*r*gs[lane*4+3] + gb[lane*4+3];
    *(float4*)(Qo + (long long)row*DD + lane*4) = o;
}

// ---------------- fused causal softmax + CAPE (bf16 scores/E in, bf16 probs out) ----------------
__global__ void softcape_k(const __nv_bfloat16* __restrict__ sc, __nv_bfloat16* __restrict__ ph,
                           const __nv_bfloat16* __restrict__ E, float* __restrict__ cape){
    __shared__ float es[8][ML];
    __shared__ float gsm[8][32][17];
    int w    = threadIdx.x>>5;
    int lane = threadIdx.x & 31;
    int row  = blockIdx.x*8 + w;
    int qi = row & (LL-1);
    const __nv_bfloat16* p = sc + (long long)row*LL;
    __nv_bfloat16* po = ph + (long long)row*LL;
    const __nv_bfloat16* er = E + (long long)row*ML;
    #pragma unroll
    for (int t=0;t<16;t++) es[w][t*32+lane] = __bfloat162float(er[t*32+lane]);

    int nv = qi+1;
    float vals[16];
    float mx = -3.4e38f;
    #pragma unroll
    for (int t=0;t<16;t++){
        int j = t*32+lane;
        float s = (j<nv) ? __bfloat162float(p[j]) : -3.4e38f;
        vals[t]=s; mx = fmaxf(mx, s);
    }
    mx = wredmax(mx);
    float sum = 0.f;
    #pragma unroll
    for (int t=0;t<16;t++){
        int j = t*32+lane;
        float e = (j<nv) ? __expf(vals[t]-mx) : 0.f;
        vals[t]=e; sum += e;
    }
    sum = wredsum(sum);
    float inv = 1.0f/sum;
    #pragma unroll
    for (int t=0;t<16;t++){
        int j = t*32+lane;
        float pv = vals[t]*inv;
        po[j] = __float2bfloat16(pv);
        float g = 1.0f/(1.0f+__expf(pv));   // 1 - sigmoid(pv); masked pv=0 -> 0.5 (matches ref)
        gsm[w][j>>4][j&15] = g;
    }
    __syncwarp();
    float cs = 0.f;
    #pragma unroll
    for (int t=0;t<16;t++) cs += gsm[w][lane][t];
    float sfx = cs;
    #pragma unroll
    for (int off=1;off<32;off<<=1){
        float o = __shfl_down_sync(0xffffffffu, sfx, off);
        if (lane+off < 32) sfx += o;
    }
    float tail = sfx - cs;
    float run = 0.f, acc = 0.f;
    #pragma unroll
    for (int t=15;t>=0;t--){
        run += gsm[w][lane][t];
        float P = run + tail;
        P = fminf(P, (float)(ML-1));
        float Pf = floorf(P);
        float fr = P - Pf;
        int pi = (int)Pf;
        int pc = (int)ceilf(P);
        float ef = es[w][pi];
        float ec = es[w][pc];
        acc += fr*ec + (1.0f-fr)*ef;
    }
    acc = wredsum(acc);
    if (lane==0) cape[row] = acc * (1.0f/LL);
}

// ---------------- final: dot of pre-LN'd feats with pos/neg item embeddings ----------------
__global__ void final_k(const float* __restrict__ feats, const float* __restrict__ item,
                        const int* __restrict__ pos, const int* __restrict__ neg,
                        float* __restrict__ out){
    int row  = blockIdx.x*8 + (threadIdx.x>>5);
    int lane = threadIdx.x & 31;
    float4 f = *(const float4*)(feats + (long long)row*DD + lane*4);
    int pi = pos[row], ni = neg[row];
    float4 pe = *(const float4*)(item + (long long)pi*DD + lane*4);
    float4 ne = *(const float4*)(item + (long long)ni*DD + lane*4);
    float dp = f.x*pe.x + f.y*pe.y + f.z*pe.z + f.w*pe.w;
    float dn = f.x*ne.x + f.y*ne.y + f.z*ne.z + f.w*ne.w;
    dp = wredsum(dp); dn = wredsum(dn);
    if (lane==0){ out[row] = dp; out[BL+row] = dn; }
}

// ---------------- pipelined TF32 GEMM, k32 steps, dynamic smem ----------------
// Base: C = act(alpha*A.B^T + bias) + res.  A [M,K], B [N,K] row-major.  K%32==0.
// 128x128 block tile, 256 thr, warp tile 64x32, 2-stage cp.async.
// DUAL: grid.x==2 selects (Bm,bias,C,ACT) / (Bm2,bias2,C2,ACT2); n0=0.
// SKIPUP: skip tiles fully above causal diagonal (scores).
// EPILN: epilogue y = alpha*A.B^T + bias + res + cape[row]; Cln = LN(y) (N==128, grid.x==1).
//        WRAW additionally writes raw y to C.
// OUTBF: non-EPILN epilogue writes bf16 pairs into (bf16*)C.
template<int ACT, int ACT2, bool DUAL, bool SKIPUP, bool EPILN, bool WRAW, bool OUTBF>
__global__ __launch_bounds__(256,2)
void gemm_p(const float* __restrict__ A, const float* __restrict__ Bm,
            const float* __restrict__ bias, const float* __restrict__ res,
            float* __restrict__ C,
            const float* __restrict__ Bm2, const float* __restrict__ bias2,
            float* __restrict__ C2,
            const float* __restrict__ lns, const float* __restrict__ lnb,
            const float* __restrict__ capev, float* __restrict__ Cln,
            int M, int N, int K,
            long long sA, long long sB, long long sC, float alpha)
{
    if (SKIPUP && (int)blockIdx.x > (int)blockIdx.y) return;
    const int bz = blockIdx.z;
    A += (long long)bz*sA;
    int actv = ACT;
    if (DUAL){
        if (blockIdx.x == 1){ Bm = Bm2; bias = bias2; C = C2; actv = ACT2; }
    } else {
        Bm += (long long)bz*sB;
        if (!OUTBF) C += (long long)bz*sC;
        if (res) res += (long long)bz*sC;
    }

    extern __shared__ float sm_g[];
    float* As = sm_g;            // 2 x [128][36]
    float* Bs = sm_g + 2*4608;   // 2 x [128][36]

    const int tid=threadIdx.x, warp=tid>>5, lane=tid&31;
    const int wm=(warp&1)*64, wn=(warp>>1)*32;
    const int m0=blockIdx.y*128;
    const int n0=DUAL ? 0 : blockIdx.x*128;
    const int ar=lane>>2, ac=lane&3;
    const int nk = K>>5;
    const int lrow = tid>>3, lc4 = (tid&7)*4;

    float acc[4][4][4];
    #pragma unroll
    for (int i=0;i<4;i++)
        #pragma unroll
        for (int j=0;j<4;j++)
            #pragma unroll
            for (int r=0;r<4;r++) acc[i][j][r]=0.f;

    // stage 0
    {
        float* as = As; float* bs = Bs;
        #pragma unroll
        for (int p=0;p<4;p++){
            int row = p*32 + lrow;
            cpa16(&as[row*36+lc4], A  + (long long)(m0+row)*K + lc4);
            cpa16(&bs[row*36+lc4], Bm + (long long)(n0+row)*K + lc4);
        }
        cp_commit();
    }

    for (int i=0;i<nk;i++){
        if (i+1<nk){
            int bn=(i+1)&1, k0=(i+1)<<5;
            float* as = As + bn*4608; float* bs = Bs + bn*4608;
            #pragma unroll
            for (int p=0;p<4;p++){
                int row = p*32 + lrow;
                cpa16(&as[row*36+lc4], A  + (long long)(m0+row)*K + k0 + lc4);
                cpa16(&bs[row*36+lc4], Bm + (long long)(n0+row)*K + k0 + lc4);
            }
            cp_commit();
            cp_wait<1>();
        } else {
            cp_wait<0>();
        }
        __syncthreads();
        const float* as = As + (i&1)*4608;
        const float* bs = Bs + (i&1)*4608;
        #pragma unroll
        for (int s8=0;s8<4;s8++){
            const int kb=s8*8;
            unsigned af[4][4];
            #pragma unroll
            for (int mi=0;mi<4;mi++){
                int r0=wm+mi*16+ar;
                af[mi][0]=fu(as[(r0  )*36+kb+ac  ]);
                af[mi][1]=fu(as[(r0+8)*36+kb+ac  ]);
                af[mi][2]=fu(as[(r0  )*36+kb+ac+4]);
                af[mi][3]=fu(as[(r0+8)*36+kb+ac+4]);
            }
            #pragma unroll
            for (int ni=0;ni<4;ni++){
                int nr=wn+ni*8+ar;
                unsigned bf[2];
                bf[0]=fu(bs[nr*36+kb+ac  ]);
                bf[1]=fu(bs[nr*36+kb+ac+4]);
                #pragma unroll
                for (int mi=0;mi<4;mi++) mma_tf32(acc[mi][ni], af[mi], bf);
            }
        }
        __syncthreads();
    }

    const int er=lane>>2, ec=(lane&3)*2;
    if (!EPILN){
        #pragma unroll
        for (int mi=0;mi<4;mi++){
            #pragma unroll
            for (int half=0; half<2; half++){
                long long gm = m0 + wm + mi*16 + er + half*8;
                long long gbase = OUTBF ? ((long long)bz*sC + gm*(long long)N)
                                        : (gm*(long long)N);
                const float* rrow = res ? (res + gm*(long long)N) : nullptr;
                #pragma unroll
                for (int ni=0;ni<4;ni++){
                    int gn = n0 + wn + ni*8 + ec;
                    float v0 = acc[mi][ni][half*2+0]*alpha;
                    float v1 = acc[mi][ni][half*2+1]*alpha;
                    if (bias){ v0 += bias[gn]; v1 += bias[gn+1]; }
                    if (actv==1){ v0 = fmaxf(v0,0.f); v1 = fmaxf(v1,0.f); }
                    if (actv==2){ v0 = v0/(1.0f+__expf(-v0)); v1 = v1/(1.0f+__expf(-v1)); }
                    if (rrow){ v0 += rrow[gn]; v1 += rrow[gn+1]; }
                    if (OUTBF){
                        *(unsigned*)(((__nv_bfloat16*)C) + gbase + gn) = pbf2(v0, v1);
                    } else {
                        float2 o; o.x=v0; o.y=v1;
                        *(float2*)(C + gbase + gn) = o;
                    }
                }
            }
        }
    } else {
        // fused LayerNorm epilogue (N==128, full row per CTA)
        __shared__ float2 red[128][4];
        const int wnidx = warp>>1;
        #pragma unroll
        for (int mi=0;mi<4;mi++){
            #pragma unroll
            for (int half=0; half<2; half++){
                int r = wm + mi*16 + er + half*8;
                long long gm = m0 + r;
                const float* rrow = res ? (res + gm*(long long)N) : nullptr;
                float cv = capev ? capev[gm] : 0.f;
                float s1=0.f, s2=0.f;
                #pragma unroll
                for (int ni=0;ni<4;ni++){
                    #pragma unroll
                    for (int u=0;u<2;u++){
                        int gn = wn + ni*8 + ec + u;
                        float v0 = acc[mi][ni][half*2+u]*alpha;
                        if (bias) v0 += bias[gn];
                        if (rrow) v0 += rrow[gn];
                        v0 += cv;
                        acc[mi][ni][half*2+u] = v0;
                        s1 += v0; s2 += v0*v0;
                    }
                }
                s1 += __shfl_xor_sync(0xffffffffu, s1, 1);
                s2 += __shfl_xor_sync(0xffffffffu, s2, 1);
                s1 += __shfl_xor_sync(0xffffffffu, s1, 2);
                s2 += __shfl_xor_sync(0xffffffffu, s2, 2);
                if ((lane&3)==0) red[r][wnidx] = make_float2(s1, s2);
            }
        }
        __syncthreads();
        #pragma unroll
        for (int mi=0;mi<4;mi++){
            #pragma unroll
            for (int half=0; half<2; half++){
                int r = wm + mi*16 + er + half*8;
                long long gm = m0 + r;
                float2 p0=red[r][0], p1=red[r][1], p2=red[r][2], p3=red[r][3];
                float S1 = p0.x+p1.x+p2.x+p3.x;
                float S2 = p0.y+p1.y+p2.y+p3.y;
                float mean = S1*(1.0f/DD);
                float var  = S2*(1.0f/DD) - mean*mean;
                float rr   = rsqrtf(var + 1e-8f);
                float* lrow = Cln + gm*(long long)N;
                float* crow = WRAW ? (C + gm*(long long)N) : nullptr;
                #pragma unroll
                for (int ni=0;ni<4;ni++){
                    int gn = wn + ni*8 + ec;
                    float v0 = acc[mi][ni][half*2+0];
                    float v1 = acc[mi][ni][half*2+1];
                    float o0 = (v0-mean)*rr*lns[gn  ] + lnb[gn  ];
                    float o1 = (v1-mean)*rr*lns[gn+1] + lnb[gn+1];
                    *(float2*)(lrow + gn) = make_float2(o0, o1);
                    if (WRAW) *(float2*)(crow + gn) = make_float2(v0, v1);
                }
            }
        }
    }
}

// ---------------- bf16 single-shot GEMM for E = qp @ pos_emb (bf16 out) ----------------
__global__ __launch_bounds__(256,2)
void gemm_e(const float* __restrict__ qp, const float* __restrict__ pe,
            __nv_bfloat16* __restrict__ E)
{
    extern __shared__ __nv_bfloat16 sm_e[];
    __nv_bfloat16* AS = sm_e;            // [128 m][136 k]
    __nv_bfloat16* BS = sm_e + 128*136;  // [128 n][136 k]

    const int tid=threadIdx.x, warp=tid>>5, lane=tid&31;
    const int n0=blockIdx.x*128;
    const long long m0=(long long)blockIdx.y*128;
    const int wm=(warp&1)*64, wn=(warp>>1)*32;
    const int ar=lane>>2, ac=lane&3;

    #pragma unroll
    for (int p=0;p<16;p++){
        int f=p*256+tid;
        int m=f>>5, k4=(f&31)*4;
        float4 a = *(const float4*)(qp + (m0+m)*DD + k4);
        uint2 u; u.x=pbf2(a.x,a.y); u.y=pbf2(a.z,a.w);
        *(uint2*)&AS[m*136+k4] = u;
    }
    #pragma unroll
    for (int p=0;p<16;p++){
        int f=p*256+tid;
        int n=f&127, kb=(f>>7)*4;
        float b0=pe[(kb+0)*ML+n0+n], b1=pe[(kb+1)*ML+n0+n];
        float b2=pe[(kb+2)*ML+n0+n], b3=pe[(kb+3)*ML+n0+n];
        uint2 u; u.x=pbf2(b0,b1); u.y=pbf2(b2,b3);
        *(uint2*)&BS[n*136+kb] = u;
    }
    __syncthreads();

    float acc[4][4][4];
    #pragma unroll
    for (int i=0;i<4;i++)
        #pragma unroll
        for (int j=0;j<4;j++)
            #pragma unroll
            for (int r=0;r<4;r++) acc[i][j][r]=0.f;

    #pragma unroll
    for (int ks=0;ks<8;ks++){
        const int kc=ks*16;
        unsigned af[4][4];
        #pragma unroll
        for (int mi=0;mi<4;mi++){
            int r0=wm+mi*16+ar;
            af[mi][0]=*(const unsigned*)&AS[(r0  )*136+kc+ac*2  ];
            af[mi][1]=*(const unsigned*)&AS[(r0+8)*136+kc+ac*2  ];
            af[mi][2]=*(const unsigned*)&AS[(r0  )*136+kc+8+ac*2];
            af[mi][3]=*(const unsigned*)&AS[(r0+8)*136+kc+8+ac*2];
        }
        #pragma unroll
        for (int ni=0;ni<4;ni++){
            int n=wn+ni*8+ar;
            unsigned bf[2];
            bf[0]=*(const unsigned*)&BS[n*136+kc+ac*2  ];
            bf[1]=*(const unsigned*)&BS[n*136+kc+8+ac*2];
            #pragma unroll
            for (int mi=0;mi<4;mi++) mma_bf16(acc[mi][ni], af[mi], bf);
        }
    }

    const int er=lane>>2, ec=(lane&3)*2;
    #pragma unroll
    for (int mi=0;mi<4;mi++){
        #pragma unroll
        for (int half=0; half<2; half++){
            long long gm = m0 + wm + mi*16 + er + half*8;
            __nv_bfloat16* crow = E + gm*(long long)ML;
            #pragma unroll
            for (int ni=0;ni<4;ni++){
                int gn = n0 + wn + ni*8 + ec;
                *(unsigned*)(crow + gn) = pbf2(acc[mi][ni][half*2+0], acc[mi][ni][half*2+1]);
            }
        }
    }
}

// ---------------- bf16 AV GEMM: mha = probs(bf16) @ v, double-buffered ----------------
__global__ __launch_bounds__(256,2)
void av_bf16(const __nv_bfloat16* __restrict__ P, const float* __restrict__ v,
             float* __restrict__ mha)
{
    const int b=blockIdx.y, m0=blockIdx.x*128;
    const __nv_bfloat16* Pb = P + (long long)b*LL*LL;
    const float* vb = v + (long long)b*LL*DD;
    float* mb = mha + (long long)b*LL*DD;

    __shared__ __align__(16) __nv_bfloat16 AS[2][128*40];
    __shared__ __align__(16) __nv_bfloat16 VS[2][128*40];

    const int tid=threadIdx.x, warp=tid>>5, lane=tid&31;
    const int wm=(warp&1)*64, wn=(warp>>1)*32;
    const int ar=lane>>2, ac=lane&3;
    const int nk=(m0+128)>>5;

    float acc[4][4][4];
    #pragma unroll
    for (int i=0;i<4;i++)
        #pragma unroll
        for (int j=0;j<4;j++)
            #pragma unroll
            for (int r=0;r<4;r++) acc[i][j][r]=0.f;

    uint2 ra[4], rb[4];

    #pragma unroll
    for (int p=0;p<4;p++){
        int f=p*256+tid; int d=f&127; int kb=(f>>7)*4;
        float f0=vb[(long long)(kb+0)*DD+d], f1=vb[(long long)(kb+1)*DD+d];
        float f2=vb[(long long)(kb+2)*DD+d], f3=vb[(long long)(kb+3)*DD+d];
        ra[p].x=pbf2(f0,f1); ra[p].y=pbf2(f2,f3);
    }
    #pragma unroll
    for (int p=0;p<2;p++){
        int f=p*256+tid; int row=f>>2, c8=(f&3)*8;
        cpa16(&AS[0][row*40+c8], Pb + (long long)(m0+row)*LL + c8);
    }
    cp_commit();
    #pragma unroll
    for (int p=0;p<4;p++){
        int f=p*256+tid; int d=f&127; int kb=(f>>7)*4;
        *(uint2*)&VS[0][d*40+kb] = ra[p];
    }
    cp_wait<0>();
    __syncthreads();

    for (int i=0;i<nk;i++){
        if (i+1<nk){
            int k0=(i+1)<<5;
            #pragma unroll
            for (int p=0;p<4;p++){
                int f=p*256+tid; int d=f&127; int kb=(f>>7)*4;
                float f0=vb[(long long)(k0+kb+0)*DD+d], f1=vb[(long long)(k0+kb+1)*DD+d];
                float f2=vb[(long long)(k0+kb+2)*DD+d], f3=vb[(long long)(k0+kb+3)*DD+d];
                rb[p].x=pbf2(f0,f1); rb[p].y=pbf2(f2,f3);
            }
            #pragma unroll
            for (int p=0;p<2;p++){
                int f=p*256+tid; int row=f>>2, c8=(f&3)*8;
                cpa16(&AS[(i+1)&1][row*40+c8], Pb + (long long)(m0+row)*LL + k0 + c8);
            }
            cp_commit();
        }
        const int bc=i&1;
        #pragma unroll
        for (int ks=0;ks<2;ks++){
            const int kc=ks*16;
            unsigned af[4][4];
            #pragma unroll
            for (int mi=0;mi<4;mi++){
                int r0=wm+mi*16+ar;
                af[mi][0]=*(const unsigned*)&AS[bc][(r0  )*40+kc+ac*2  ];
                af[mi][1]=*(const unsigned*)&AS[bc][(r0+8)*40+kc+ac*2  ];
                af[mi][2]=*(const unsigned*)&AS[bc][(r0  )*40+kc+8+ac*2];
                af[mi][3]=*(const unsigned*)&AS[bc][(r0+8)*40+kc+8+ac*2];
            }
            #pragma unroll
            for (int ni=0;ni<4;ni++){
                int n=wn+ni*8+ar;
                unsigned bf[2];
                bf[0]=*(const unsigned*)&VS[bc][n*40+kc+ac*2  ];
                bf[1]=*(const unsigned*)&VS[bc][n*40+kc+8+ac*2];
                #pragma unroll
                for (int mi=0;mi<4;mi++) mma_bf16(acc[mi][ni], af[mi], bf);
            }
        }
        __syncthreads();
        if (i+1<nk){
            #pragma unroll
            for (int p=0;p<4;p++){
                int f=p*256+tid; int d=f&127; int kb=(f>>7)*4;
                *(uint2*)&VS[(i+1)&1][d*40+kb] = rb[p];
            }
            cp_wait<0>();
            __syncthreads();
        }
    }

    const int er=lane>>2, ec=(lane&3)*2;
    #pragma unroll
    for (int mi=0;mi<4;mi++){
        #pragma unroll
        for (int half=0; half<2; half++){
            long long gm = m0 + wm + mi*16 + er + half*8;
            float* crow = mb + gm*(long long)DD;
            #pragma unroll
            for (int ni=0;ni<4;ni++){
                int gn = wn + ni*8 + ec;
                float2 o; o.x=acc[mi][ni][half*2+0]; o.y=acc[mi][ni][half*2+1];
                *(float2*)(crow + gn) = o;
            }
        }
    }
}

// ---------------- host orchestration ----------------
extern "C" void kernel_launch(void* const* d_in, const int* in_sizes, int n_in,
                              void* d_out, int out_size){
    (void)in_sizes; (void)n_in; (void)out_size;
    const float* item   = (const float*)d_in[0];
    const float* posemb = (const float*)d_in[1];
    const float* pre_w  = (const float*)d_in[2];
    const float* pre_b  = (const float*)d_in[3];
    const float* ln1_s  = (const float*)d_in[4];
    const float* ln1_b  = (const float*)d_in[5];
    const float* in_w   = (const float*)d_in[6];
    const float* in_b   = (const float*)d_in[7];
    const float* out_w  = (const float*)d_in[8];
    const float* out_b  = (const float*)d_in[9];
    const float* ln2_s  = (const float*)d_in[10];
    const float* ln2_b  = (const float*)d_in[11];
    const float* c1_w   = (const float*)d_in[12];
    const float* c1_b   = (const float*)d_in[13];
    const float* c2_w   = (const float*)d_in[14];
    const float* c2_b   = (const float*)d_in[15];
    const float* lnf_s  = (const float*)d_in[16];
    const float* lnf_b  = (const float*)d_in[17];
    const int* logs = (const int*)d_in[19];
    const int* poss = (const int*)d_in[20];
    const int* negs = (const int*)d_in[21];
    float* out = (float*)d_out;

    float *seqs,*Q,*q,*k,*v,*qp,*mha,*tmp,*cape;
    __nv_bfloat16 *scoresh,*attnh,*Eh;
    cudaGetSymbolAddress((void**)&seqs, g_seqs);
    cudaGetSymbolAddress((void**)&Q,    g_Q);
    cudaGetSymbolAddress((void**)&q,    g_q);
    cudaGetSymbolAddress((void**)&k,    g_k);
    cudaGetSymbolAddress((void**)&v,    g_v);
    cudaGetSymbolAddress((void**)&qp,   g_qp);
    cudaGetSymbolAddress((void**)&mha,  g_mha);
    cudaGetSymbolAddress((void**)&tmp,  g_tmp);
    cudaGetSymbolAddress((void**)&scoresh, g_scoresh);
    cudaGetSymbolAddress((void**)&attnh,   g_attnh);
    cudaGetSymbolAddress((void**)&Eh,      g_Eh);
    cudaGetSymbolAddress((void**)&cape, g_cape);

    const int ROWB = BL/8;
    const float scale = 0.08838834764831845f; // 1/sqrt(128)
    const int GPSM = 2*4608*4*2;    // 73,728 B dynamic smem for gemm_p
    const int ESM  = 2*128*136*2;   // 69,632 B dynamic smem for gemm_e

    static int once = 0;
    if (!once){
        cudaFuncSetAttribute(gemm_p<0,2,true,false,false,false,false>,  cudaFuncAttributeMaxDynamicSharedMemorySize, GPSM);
        cudaFuncSetAttribute(gemm_p<0,0,true,false,false,false,false>,  cudaFuncAttributeMaxDynamicSharedMemorySize, GPSM);
        cudaFuncSetAttribute(gemm_p<0,0,false,true,false,false,true>,   cudaFuncAttributeMaxDynamicSharedMemorySize, GPSM);
        cudaFuncSetAttribute(gemm_p<0,0,false,false,true,false,false>,  cudaFuncAttributeMaxDynamicSharedMemorySize, GPSM);
        cudaFuncSetAttribute(gemm_p<0,0,false,false,true,true,false>,   cudaFuncAttributeMaxDynamicSharedMemorySize, GPSM);
        cudaFuncSetAttribute(gemm_p<1,0,false,false,false,false,false>, cudaFuncAttributeMaxDynamicSharedMemorySize, GPSM);
        cudaFuncSetAttribute(gemm_e, cudaFuncAttributeMaxDynamicSharedMemorySize, ESM);
        once = 1;
    }

    // embed + fused LN1(block 0): writes seqs and Q
    embed_ln_k<<<ROWB,256>>>(item, logs, ln1_s, ln1_b, seqs, Q);

    for (int i=0;i<2;i++){
        const float* wq = in_w + (long long)i*3*DD*DD;
        const float* wk = wq + DD*DD;
        const float* wv = wk + DD*DD;
        const float* bq = in_b + (long long)i*3*DD;
        const float* bk = bq + DD;
        const float* bv = bk + DD;

        // dual GEMMs: (q, qp) from Q;  (k, v) from seqs
        dim3 gd(2, BL/128);
        gemm_p<0,2,true,false,false,false,false><<<gd,256,GPSM>>>(Q, wq, bq, nullptr, q,
                                                pre_w, pre_b, qp,
                                                nullptr,nullptr,nullptr,nullptr,
                                                BL, DD, DD, 0,0,0, 1.f);
        gemm_p<0,0,true,false,false,false,false><<<gd,256,GPSM>>>(seqs, wk, bk, nullptr, k,
                                                wv, bv, v,
                                                nullptr,nullptr,nullptr,nullptr,
                                                BL, DD, DD, 0,0,0, 1.f);

        // E = qp @ pos_emb  (bf16 tensor cores, single-shot K=128, bf16 out)
        gemm_e<<<dim3(4, BL/128),256,ESM>>>(qp, posemb, Eh);

        // scores = q.k^T * scale  (skip fully-masked upper tiles, bf16 out)
        dim3 gsc(4,4,BB);
        gemm_p<0,0,false,true,false,false,true><<<gsc,256,GPSM>>>(q, k, nullptr, nullptr,
            (float*)scoresh,
            nullptr,nullptr,nullptr,
            nullptr,nullptr,nullptr,nullptr,
            LL, LL, DD, (long long)LL*DD, (long long)LL*DD, (long long)LL*LL, scale);

        // fused softmax + CAPE (bf16 scores/E in, bf16 probs + fp32 cape out)
        softcape_k<<<ROWB,256>>>(scoresh, attnh, Eh, cape);

        // mha = probs(bf16) @ v   (causal K-limit per m-tile)
        av_bf16<<<dim3(4,BB),256>>>(attnh, v, mha);

        // X = LN2(Q + mha.out_w^T + out_b + cape)  -> written to Q buffer
        dim3 gl(1, BL/128);
        gemm_p<0,0,false,false,true,false,false><<<gl,256,GPSM>>>(mha, out_w+(long long)i*DD*DD,
                                                 out_b+i*DD, Q, seqs /*unused*/,
                                                 nullptr,nullptr,nullptr,
                                                 ln2_s+i*DD, ln2_b+i*DD, cape, Q,
                                                 BL, DD, DD, 0,0,0, 1.f);

        // FFN: h = relu(X.c1^T + b1)
        gemm_p<1,0,false,false,false,false,false><<<gl,256,GPSM>>>(Q, c1_w+(long long)i*DD*DD,
                                                 c1_b+i*DD, nullptr, tmp,
                                                 nullptr,nullptr,nullptr,
                                                 nullptr,nullptr,nullptr,nullptr,
                                                 BL, DD, DD, 0,0,0, 1.f);
        // seqs_raw = X + h.c2^T + b2 ; fused LN of NEXT stage:
        //   i==0: seqs written raw (for block-1 k/v), Q = LN1_b1(seqs_raw)
        //   i==1: feats = LNf(seqs_raw) -> g_v (raw not needed)
        if (i==0){
            gemm_p<0,0,false,false,true,true,false><<<gl,256,GPSM>>>(tmp, c2_w+(long long)i*DD*DD,
                                                 c2_b+i*DD, Q, seqs,
                                                 nullptr,nullptr,nullptr,
                                                 ln1_s+DD, ln1_b+DD, nullptr, Q,
                                                 BL, DD, DD, 0,0,0, 1.f);
        } else {
            gemm_p<0,0,false,false,true,false,false><<<gl,256,GPSM>>>(tmp, c2_w+(long long)i*DD*DD,
                                                 c2_b+i*DD, Q, seqs /*unused*/,
                                                 nullptr,nullptr,nullptr,
                                                 lnf_s, lnf_b, nullptr, v,
                                                 BL, DD, DD, 0,0,0, 1.f);
        }
    }

    // final: dot(feats, item_emb[pos/neg])
    final_k<<<ROWB,256>>>(v, item, poss, negs, out);
}